// round 1
// baseline (speedup 1.0000x reference)
#include <cuda_runtime.h>
#include <cstdint>

// Problem constants (fixed by setup_inputs)
#define B_   8
#define QL   1024
#define SL   2048
#define DM   1024
#define H_   16
#define DH   64
#define QT   128          // q rows per CTA
#define STT  128          // s cols per chunk
#define NCHUNK (SL/STT)   // 16

// smem strides (floats) chosen for conflict-free mma fragment loads
#define QS_S 68   // stride%32==4 -> A-frag banks 4g+lt distinct
#define KS_S 68   // B-frag (QK) banks 4g+lt distinct
#define VS_S 72   // stride%32==8 -> B-frag (PV) banks 8*lt+g distinct
#define PS_S 132  // stride%32==4 -> A-frag (PV) conflict-free, float4-aligned

#define SMEM_FLOATS (QT*QS_S + STT*KS_S + STT*VS_S + QT*PS_S + SL + QT + QT)

__device__ __forceinline__ float tf32r(float x) {
    uint32_t u;
    asm("cvt.rna.tf32.f32 %0, %1;" : "=r"(u) : "f"(x));
    return __uint_as_float(u);
}

__device__ __forceinline__ void mma8(float d[4], const uint32_t a[4], const uint32_t b[2]) {
    asm("mma.sync.aligned.m16n8k8.row.col.f32.tf32.tf32.f32 "
        "{%0,%1,%2,%3},{%4,%5,%6,%7},{%8,%9},{%0,%1,%2,%3};\n"
        : "+f"(d[0]), "+f"(d[1]), "+f"(d[2]), "+f"(d[3])
        : "r"(a[0]), "r"(a[1]), "r"(a[2]), "r"(a[3]), "r"(b[0]), "r"(b[1]));
}

// QK^T for one 128x128 chunk. Warp grid 4x2: warp tile 32(q) x 64(s).
__device__ __forceinline__ void qk_chunk(const float* __restrict__ Qs,
                                         const float* __restrict__ Ks,
                                         float acc[2][8][4],
                                         int wm, int wn, int g, int lt) {
    #pragma unroll
    for (int kk = 0; kk < 8; kk++) {
        uint32_t afr[2][4];
        #pragma unroll
        for (int mi = 0; mi < 2; mi++) {
            int r = wm * 32 + mi * 16 + g;
            afr[mi][0] = __float_as_uint(Qs[r * QS_S + kk * 8 + lt]);
            afr[mi][1] = __float_as_uint(Qs[(r + 8) * QS_S + kk * 8 + lt]);
            afr[mi][2] = __float_as_uint(Qs[r * QS_S + kk * 8 + lt + 4]);
            afr[mi][3] = __float_as_uint(Qs[(r + 8) * QS_S + kk * 8 + lt + 4]);
        }
        #pragma unroll
        for (int ni = 0; ni < 8; ni++) {
            int c = wn * 64 + ni * 8 + g;
            uint32_t bfr[2];
            bfr[0] = __float_as_uint(Ks[c * KS_S + kk * 8 + lt]);
            bfr[1] = __float_as_uint(Ks[c * KS_S + kk * 8 + lt + 4]);
            mma8(acc[0][ni], afr[0], bfr);
            mma8(acc[1][ni], afr[1], bfr);
        }
    }
}

extern "C" __global__ void __launch_bounds__(256, 1)
mha_fused_kernel(const float* __restrict__ Qg, const float* __restrict__ Kg,
                 const float* __restrict__ Vg, const int* __restrict__ Mg,
                 float* __restrict__ Og, float* __restrict__ Ag, int write_attn) {
    extern __shared__ float smf[];
    float* Qs = smf;
    float* Ks = Qs + QT * QS_S;
    float* Vs = Ks + STT * KS_S;
    float* Ps = Vs + STT * VS_S;
    float* Ms = Ps + QT * PS_S;   // mask as float, whole row of S
    float* Rs = Ms + SL;          // rowsum[128]
    float* Is = Rs + QT;          // 1/rowsum

    const int tid = threadIdx.x;
    const int lane = tid & 31, wid = tid >> 5;
    const int g = lane >> 2, lt = lane & 3;
    const int wm = wid >> 1, wn = wid & 1;
    const int b = blockIdx.z, h = blockIdx.y, q0 = blockIdx.x * QT;

    // ---- init: mask row, rowsum, Q tile (scaled by 1/sqrt(Dh), tf32-rounded) ----
    for (int j = tid; j < SL; j += 256) Ms[j] = (float)Mg[b * SL + j];
    if (tid < QT) Rs[tid] = 0.f;
    {
        const float* gq = Qg + ((size_t)(b * QL + q0) * DM) + h * DH;
        for (int i = tid; i < QT * DH / 4; i += 256) {
            int r = i >> 4, c4 = (i & 15) << 2;
            float4 v = *(const float4*)(gq + (size_t)r * DM + c4);
            float4 w;
            w.x = tf32r(v.x * 0.125f); w.y = tf32r(v.y * 0.125f);
            w.z = tf32r(v.z * 0.125f); w.w = tf32r(v.w * 0.125f);
            *(float4*)(Qs + r * QS_S + c4) = w;
        }
    }

    // ================= Phase 1: rowsums of exp(z)*mask =================
    for (int sc = 0; sc < NCHUNK; sc++) {
        const int s0 = sc * STT;
        __syncthreads();  // guard Ks reuse (and initial smem init)
        const float* gk = Kg + ((size_t)(b * SL + s0) * DM) + h * DH;
        for (int i = tid; i < STT * DH / 4; i += 256) {
            int r = i >> 4, c4 = (i & 15) << 2;
            float4 v = *(const float4*)(gk + (size_t)r * DM + c4);
            float4 w;
            w.x = tf32r(v.x); w.y = tf32r(v.y); w.z = tf32r(v.z); w.w = tf32r(v.w);
            *(float4*)(Ks + r * KS_S + c4) = w;
        }
        __syncthreads();

        float acc[2][8][4];
        #pragma unroll
        for (int mi = 0; mi < 2; mi++)
            #pragma unroll
            for (int ni = 0; ni < 8; ni++)
                #pragma unroll
                for (int j = 0; j < 4; j++) acc[mi][ni][j] = 0.f;

        qk_chunk(Qs, Ks, acc, wm, wn, g, lt);

        #pragma unroll
        for (int mi = 0; mi < 2; mi++)
            #pragma unroll
            for (int half = 0; half < 2; half++) {
                int r = wm * 32 + mi * 16 + g + half * 8;
                float rs = 0.f;
                #pragma unroll
                for (int ni = 0; ni < 8; ni++) {
                    int c = wn * 64 + ni * 8 + 2 * lt;
                    float e0 = __expf(acc[mi][ni][half * 2 + 0]) * Ms[s0 + c];
                    float e1 = __expf(acc[mi][ni][half * 2 + 1]) * Ms[s0 + c + 1];
                    rs += e0 + e1;
                }
                rs += __shfl_xor_sync(0xffffffffu, rs, 1);
                rs += __shfl_xor_sync(0xffffffffu, rs, 2);
                if (lt == 0) atomicAdd(&Rs[r], rs);
            }
    }

    __syncthreads();
    if (tid < QT) Is[tid] = 1.0f / (Rs[tid] + 1e-13f);

    // ================= Phase 2: recompute, write normalized attn, PV =================
    float oacc[8][4];  // warp tile 16(q) x 64(dv): warp w owns rows 16w..16w+15
    #pragma unroll
    for (int ni = 0; ni < 8; ni++)
        #pragma unroll
        for (int j = 0; j < 4; j++) oacc[ni][j] = 0.f;

    for (int sc = 0; sc < NCHUNK; sc++) {
        const int s0 = sc * STT;
        __syncthreads();  // guard Ks/Vs/Ps reuse vs previous chunk's PV + inv compute
        const float* gk = Kg + ((size_t)(b * SL + s0) * DM) + h * DH;
        const float* gv = Vg + ((size_t)(b * SL + s0) * DM) + h * DH;
        for (int i = tid; i < STT * DH / 4; i += 256) {
            int r = i >> 4, c4 = (i & 15) << 2;
            float4 v = *(const float4*)(gk + (size_t)r * DM + c4);
            float4 w;
            w.x = tf32r(v.x); w.y = tf32r(v.y); w.z = tf32r(v.z); w.w = tf32r(v.w);
            *(float4*)(Ks + r * KS_S + c4) = w;
            float4 u = *(const float4*)(gv + (size_t)r * DM + c4);
            float4 x;
            x.x = tf32r(u.x); x.y = tf32r(u.y); x.z = tf32r(u.z); x.w = tf32r(u.w);
            *(float4*)(Vs + r * VS_S + c4) = x;
        }
        __syncthreads();

        float acc[2][8][4];
        #pragma unroll
        for (int mi = 0; mi < 2; mi++)
            #pragma unroll
            for (int ni = 0; ni < 8; ni++)
                #pragma unroll
                for (int j = 0; j < 4; j++) acc[mi][ni][j] = 0.f;

        qk_chunk(Qs, Ks, acc, wm, wn, g, lt);

        // normalized p -> Ps (full fp32 precision for the attention output)
        #pragma unroll
        for (int mi = 0; mi < 2; mi++)
            #pragma unroll
            for (int half = 0; half < 2; half++) {
                int r = wm * 32 + mi * 16 + g + half * 8;
                float iv = Is[r];
                #pragma unroll
                for (int ni = 0; ni < 8; ni++) {
                    int c = wn * 64 + ni * 8 + 2 * lt;
                    float2 pv;
                    pv.x = __expf(acc[mi][ni][half * 2 + 0]) * Ms[s0 + c] * iv;
                    pv.y = __expf(acc[mi][ni][half * 2 + 1]) * Ms[s0 + c + 1] * iv;
                    *(float2*)(Ps + r * PS_S + c) = pv;
                }
            }
        __syncthreads();

        // coalesced streaming write of the normalized attention tile
        if (write_attn) {
            for (int i = tid; i < QT * STT / 4; i += 256) {
                int r = i >> 5, c4 = (i & 31) << 2;
                float4 v = *(const float4*)(Ps + r * PS_S + c4);
                __stcs((float4*)(Ag + (size_t)((b * QL + q0 + r) * H_ + h) * SL + s0 + c4), v);
            }
        }

        // PV: O[128x64] += P[128x128] @ V[128x64]
        #pragma unroll
        for (int kk = 0; kk < 16; kk++) {
            uint32_t afr[4];
            int r = wid * 16 + g;
            afr[0] = __float_as_uint(tf32r(Ps[r * PS_S + kk * 8 + lt]));
            afr[1] = __float_as_uint(tf32r(Ps[(r + 8) * PS_S + kk * 8 + lt]));
            afr[2] = __float_as_uint(tf32r(Ps[r * PS_S + kk * 8 + lt + 4]));
            afr[3] = __float_as_uint(tf32r(Ps[(r + 8) * PS_S + kk * 8 + lt + 4]));
            #pragma unroll
            for (int ni = 0; ni < 8; ni++) {
                uint32_t bfr[2];
                bfr[0] = __float_as_uint(Vs[(kk * 8 + lt) * VS_S + ni * 8 + g]);
                bfr[1] = __float_as_uint(Vs[(kk * 8 + lt + 4) * VS_S + ni * 8 + g]);
                mma8(oacc[ni], afr, bfr);
            }
        }
    }

    // ---- write O tile ----
    {
        int r = wid * 16 + g;
        float* go = Og + ((size_t)(b * QL + q0 + r) * DM) + h * DH;
        #pragma unroll
        for (int ni = 0; ni < 8; ni++) {
            int c = ni * 8 + 2 * lt;
            float2 v0; v0.x = oacc[ni][0]; v0.y = oacc[ni][1];
            float2 v1; v1.x = oacc[ni][2]; v1.y = oacc[ni][3];
            __stcs((float2*)(go + c), v0);
            __stcs((float2*)(go + (size_t)8 * DM + c), v1);
        }
    }
}

extern "C" void kernel_launch(void* const* d_in, const int* in_sizes, int n_in,
                              void* d_out, int out_size) {
    const float* Qg = (const float*)d_in[0];
    const float* Kg = (const float*)d_in[1];
    const float* Vg = (const float*)d_in[2];
    const int*   Mg = (const int*)d_in[3];

    float* Og = (float*)d_out;
    float* Ag = Og + (size_t)B_ * QL * DM;  // attention follows `out` in d_out

    const long long need = (long long)B_ * QL * DM + (long long)B_ * QL * H_ * SL;
    int write_attn = ((long long)out_size >= need) ? 1 : 0;

    cudaFuncSetAttribute(mha_fused_kernel,
                         cudaFuncAttributeMaxDynamicSharedMemorySize,
                         SMEM_FLOATS * (int)sizeof(float));

    dim3 grid(QL / QT, H_, B_);
    mha_fused_kernel<<<grid, 256, SMEM_FLOATS * sizeof(float)>>>(
        Qg, Kg, Vg, Mg, Og, Ag, write_attn);
}